// round 4
// baseline (speedup 1.0000x reference)
#include <cuda_runtime.h>

#define MAXN 50000
#define MAXE 800000
#define FIN  128
#define FHID 128
#define FOUT2 64
#define SCAN_TILE 4096
#define MAXTILES 32

// ---------------- scratch (device globals; no allocation allowed) ----------
__device__ int   g_deg[MAXN];
__device__ int   g_off[MAXN + 1];
__device__ int   g_cur[MAXN];
__device__ float g_dis[MAXN];        // rsqrt(deg+1)
__device__ int   g_srcs[MAXE];
__device__ int   g_is64;
__device__ int   g_tsum[MAXTILES];
__device__ float g_xw[MAXN * FHID];  // dis ⊙ (x @ W1)
__device__ float g_h [MAXN * FHID];
__device__ float g_hw[MAXN * FOUT2]; // dis ⊙ (h @ W2)

// ---------------- packed f32x2 helpers -------------------------------------
__device__ __forceinline__ unsigned long long pack2(float lo, float hi) {
    unsigned long long r;
    asm("mov.b64 %0, {%1, %2};" : "=l"(r) : "f"(lo), "f"(hi));
    return r;
}
__device__ __forceinline__ void unpack2(unsigned long long v, float& lo, float& hi) {
    asm("mov.b64 {%0, %1}, %2;" : "=f"(lo), "=f"(hi) : "l"(v));
}
__device__ __forceinline__ void fma2(unsigned long long& d, unsigned long long a,
                                     unsigned long long b) {
    asm("fma.rn.f32x2 %0, %1, %2, %0;" : "+l"(d) : "l"(a), "l"(b));
}

// ---------------- zero + dtype detection -----------------------------------
__global__ void k_zero_detect(const void* ei, int n) {
    int i = blockIdx.x * blockDim.x + threadIdx.x;
    if (i < n) { g_deg[i] = 0; g_cur[i] = 0; }
    if (blockIdx.x == 0) {
        const long long* p = (const long long*)ei;
        int tid = threadIdx.x;
        int ok = 1;
        #pragma unroll
        for (int j = 0; j < 8; j++) {
            long long v = p[tid * 8 + j];
            if (v < 0 || v >= (long long)n) ok = 0;
        }
        int all_ok = __syncthreads_and(ok);
        if (tid == 0) g_is64 = all_ok;
    }
}

__device__ __forceinline__ int load_idx(const void* ei, long long pos, int is64) {
    if (is64) return (int)((const long long*)ei)[pos];
    return ((const int*)ei)[pos];
}

__global__ void k_hist(const void* ei, int E) {
    int e = blockIdx.x * blockDim.x + threadIdx.x;
    if (e >= E) return;
    int is64 = g_is64;
    int col = load_idx(ei, (long long)E + e, is64);
    atomicAdd(&g_deg[col], 1);
}

// ---------------- scan phase 1: per-tile exclusive scan + dis ---------------
__global__ void k_scan1(int n) {
    __shared__ int wsum[32];
    int tid  = threadIdx.x;
    int lane = tid & 31, wid = tid >> 5;
    int base = blockIdx.x * SCAN_TILE + tid * 4;

    int v[4];
    #pragma unroll
    for (int j = 0; j < 4; j++) {
        int i = base + j;
        if (i < n) {
            int d = g_deg[i];
            v[j] = d;
            g_dis[i] = rsqrtf((float)(d + 1));
        } else v[j] = 0;
    }
    int s = v[0] + v[1] + v[2] + v[3];

    int inc = s;
    #pragma unroll
    for (int d = 1; d < 32; d <<= 1) {
        int t = __shfl_up_sync(0xffffffffu, inc, d);
        if (lane >= d) inc += t;
    }
    if (lane == 31) wsum[wid] = inc;
    __syncthreads();
    if (wid == 0) {
        int w = wsum[lane];
        #pragma unroll
        for (int d = 1; d < 32; d <<= 1) {
            int t = __shfl_up_sync(0xffffffffu, w, d);
            if (lane >= d) w += t;
        }
        wsum[lane] = w;
    }
    __syncthreads();
    int excl = inc - s + (wid > 0 ? wsum[wid - 1] : 0);
    int run = excl;
    #pragma unroll
    for (int j = 0; j < 4; j++) {
        int i = base + j;
        if (i < n) g_off[i] = run;
        run += v[j];
    }
    if (tid == 0) g_tsum[blockIdx.x] = wsum[31];
}

// ---------------- scan phases 2+3 merged ------------------------------------
__global__ void k_scan23(int n, int ntiles) {
    __shared__ int sh_toff[32];
    int tid = threadIdx.x;
    if (tid < 32) {
        int t = (tid < ntiles) ? g_tsum[tid] : 0;
        int inc = t;
        #pragma unroll
        for (int d = 1; d < 32; d <<= 1) {
            int u = __shfl_up_sync(0xffffffffu, inc, d);
            if (tid >= d) inc += u;
        }
        sh_toff[tid] = inc - t;
        if (tid == 31 && blockIdx.x == 0) g_off[n] = inc;
    }
    __syncthreads();
    int i = blockIdx.x * blockDim.x + tid;
    if (i < n) g_off[i] += sh_toff[i >> 12];
}

__global__ void k_scatter(const void* ei, int E) {
    int e = blockIdx.x * blockDim.x + threadIdx.x;
    if (e >= E) return;
    int is64 = g_is64;
    int row = load_idx(ei, e, is64);
    int col = load_idx(ei, (long long)E + e, is64);
    int pos = g_off[col] + atomicAdd(&g_cur[col], 1);
    g_srcs[pos] = row;
}

// ---------------- GEMM: Y[n,FO] = scale[r] * (X[n,128] @ W[128,FO]) ---------
// 512 threads; each thread: 4 rows x 8 cols, math in packed f32x2.
template <int FO>
__global__ void __launch_bounds__(512, 1)
k_gemm(const float* __restrict__ X, const float* __restrict__ W,
       const float* __restrict__ scale, float* __restrict__ Y, int n) {
    constexpr int NT   = 512;
    constexpr int CGS  = FO / 8;          // col groups of 8 (16 or 8)
    constexpr int RG   = NT / CGS;        // 32 or 64
    constexpr int RPT  = 4;
    constexpr int ROWS = RG * RPT;        // 128 or 256
    constexpr int SXP4 = 33;              // padded float4 row stride
    constexpr int WROW4 = FO / 4;
    extern __shared__ float sh[];
    float4* sW4 = (float4*)sh;                 // 32*FO float4
    float4* sX4 = (float4*)(sh + 128 * FO);    // ROWS * SXP4 float4

    int tid  = threadIdx.x;
    int row0 = blockIdx.x * ROWS;
    const float4* W4g = (const float4*)W;
    const float4* X4g = (const float4*)X;

    for (int i = tid; i < 32 * FO; i += NT) sW4[i] = W4g[i];
    for (int i = tid; i < ROWS * 32; i += NT) {
        int r = i >> 5, c = i & 31;
        int gr = row0 + r;
        sX4[r * SXP4 + c] = (gr < n) ? X4g[gr * 32 + c]
                                     : make_float4(0.f, 0.f, 0.f, 0.f);
    }
    __syncthreads();

    int cg = tid % CGS;                // column group (8 cols)
    int rb = (tid / CGS) * RPT;        // row base within tile
    unsigned long long acc[RPT][4];
    #pragma unroll
    for (int r = 0; r < RPT; r++)
        #pragma unroll
        for (int c = 0; c < 4; c++) acc[r][c] = pack2(0.f, 0.f);

    for (int kk = 0; kk < 32; kk++) {
        unsigned long long wp[4][4];
        #pragma unroll
        for (int k = 0; k < 4; k++) {
            float4 wa = sW4[(4 * kk + k) * WROW4 + cg * 2];
            float4 wb = sW4[(4 * kk + k) * WROW4 + cg * 2 + 1];
            wp[k][0] = pack2(wa.x, wa.y);
            wp[k][1] = pack2(wa.z, wa.w);
            wp[k][2] = pack2(wb.x, wb.y);
            wp[k][3] = pack2(wb.z, wb.w);
        }
        #pragma unroll
        for (int r = 0; r < RPT; r++) {
            float4 a = sX4[(rb + r) * SXP4 + kk];
            unsigned long long a0 = pack2(a.x, a.x);
            unsigned long long a1 = pack2(a.y, a.y);
            unsigned long long a2 = pack2(a.z, a.z);
            unsigned long long a3 = pack2(a.w, a.w);
            #pragma unroll
            for (int c = 0; c < 4; c++) fma2(acc[r][c], a0, wp[0][c]);
            #pragma unroll
            for (int c = 0; c < 4; c++) fma2(acc[r][c], a1, wp[1][c]);
            #pragma unroll
            for (int c = 0; c < 4; c++) fma2(acc[r][c], a2, wp[2][c]);
            #pragma unroll
            for (int c = 0; c < 4; c++) fma2(acc[r][c], a3, wp[3][c]);
        }
    }

    float4* Y4 = (float4*)Y;
    #pragma unroll
    for (int r = 0; r < RPT; r++) {
        int gr = row0 + rb + r;
        if (gr < n) {
            float sc = scale[gr];
            float4 o0, o1;
            unpack2(acc[r][0], o0.x, o0.y); unpack2(acc[r][1], o0.z, o0.w);
            unpack2(acc[r][2], o1.x, o1.y); unpack2(acc[r][3], o1.z, o1.w);
            o0.x *= sc; o0.y *= sc; o0.z *= sc; o0.w *= sc;
            o1.x *= sc; o1.y *= sc; o1.z *= sc; o1.w *= sc;
            Y4[gr * WROW4 + cg * 2]     = o0;
            Y4[gr * WROW4 + cg * 2 + 1] = o1;
        }
    }
}

// ---------------- aggregation: warp per destination node -------------------
// in is pre-scaled by dis: out = di*(sum_{j in in(i)} in[j] + in[i]) + b
__global__ void k_agg128(const float* __restrict__ xw, const float* __restrict__ bias,
                         float* __restrict__ out, int n) {
    int warp = (blockIdx.x * blockDim.x + threadIdx.x) >> 5;
    int lane = threadIdx.x & 31;
    if (warp >= n) return;
    int node = warp;
    int s = g_off[node], e = g_off[node + 1];
    float di = g_dis[node];
    const float4* xw4 = (const float4*)xw;

    float4 acc = xw4[node * 32 + lane];   // self term (pre-scaled)
    int p = s;
    for (; p + 3 < e; p += 4) {
        int s0 = g_srcs[p], s1 = g_srcs[p + 1], s2 = g_srcs[p + 2], s3 = g_srcs[p + 3];
        float4 v0 = xw4[s0 * 32 + lane];
        float4 v1 = xw4[s1 * 32 + lane];
        float4 v2 = xw4[s2 * 32 + lane];
        float4 v3 = xw4[s3 * 32 + lane];
        acc.x += v0.x + v1.x + v2.x + v3.x;
        acc.y += v0.y + v1.y + v2.y + v3.y;
        acc.z += v0.z + v1.z + v2.z + v3.z;
        acc.w += v0.w + v1.w + v2.w + v3.w;
    }
    for (; p < e; p++) {
        int s0 = g_srcs[p];
        float4 v0 = xw4[s0 * 32 + lane];
        acc.x += v0.x; acc.y += v0.y; acc.z += v0.z; acc.w += v0.w;
    }
    float4 bb = ((const float4*)bias)[lane];
    acc.x = fmaxf(di * acc.x + bb.x, 0.f);
    acc.y = fmaxf(di * acc.y + bb.y, 0.f);
    acc.z = fmaxf(di * acc.z + bb.z, 0.f);
    acc.w = fmaxf(di * acc.w + bb.w, 0.f);
    ((float4*)out)[node * 32 + lane] = acc;
}

__global__ void k_agg64(const float* __restrict__ hw, const float* __restrict__ bias,
                        float* __restrict__ out, int n) {
    int warp = (blockIdx.x * blockDim.x + threadIdx.x) >> 5;
    int lane = threadIdx.x & 31;
    if (warp >= n) return;
    int node = warp;
    int s = g_off[node], e = g_off[node + 1];
    float di = g_dis[node];
    const float2* hw2 = (const float2*)hw;

    float2 acc = hw2[node * 32 + lane];   // self term
    int p = s;
    for (; p + 3 < e; p += 4) {
        int s0 = g_srcs[p], s1 = g_srcs[p + 1], s2 = g_srcs[p + 2], s3 = g_srcs[p + 3];
        float2 v0 = hw2[s0 * 32 + lane];
        float2 v1 = hw2[s1 * 32 + lane];
        float2 v2 = hw2[s2 * 32 + lane];
        float2 v3 = hw2[s3 * 32 + lane];
        acc.x += v0.x + v1.x + v2.x + v3.x;
        acc.y += v0.y + v1.y + v2.y + v3.y;
    }
    for (; p < e; p++) {
        int s0 = g_srcs[p];
        float2 v0 = hw2[s0 * 32 + lane];
        acc.x += v0.x; acc.y += v0.y;
    }
    float2 bb = ((const float2*)bias)[lane];
    acc.x = di * acc.x + bb.x;
    acc.y = di * acc.y + bb.y;
    ((float2*)out)[node * 32 + lane] = acc;
}

// ---------------- launch ----------------------------------------------------
extern "C" void kernel_launch(void* const* d_in, const int* in_sizes, int n_in,
                              void* d_out, int out_size) {
    const float* x  = (const float*)d_in[0];
    const void*  ei = d_in[1];
    const float* W1 = (const float*)d_in[2];
    const float* b1 = (const float*)d_in[3];
    const float* W2 = (const float*)d_in[4];
    const float* b2 = (const float*)d_in[5];
    float* out = (float*)d_out;

    int n = in_sizes[0] / FIN;
    int E = in_sizes[1] / 2;
    if (n > MAXN) n = MAXN;
    if (E > MAXE) E = MAXE;
    int ntiles = (n + SCAN_TILE - 1) / SCAN_TILE;

    float *p_xw, *p_h, *p_hw, *p_dis;
    cudaGetSymbolAddress((void**)&p_xw,  g_xw);
    cudaGetSymbolAddress((void**)&p_h,   g_h);
    cudaGetSymbolAddress((void**)&p_hw,  g_hw);
    cudaGetSymbolAddress((void**)&p_dis, g_dis);

    size_t sh128 = (size_t)(128 * 128 + 128 * 132) * sizeof(float);   // 133120
    size_t sh64  = (size_t)(128 * 64  + 256 * 132) * sizeof(float);   // 167936
    cudaFuncSetAttribute(k_gemm<128>, cudaFuncAttributeMaxDynamicSharedMemorySize, (int)sh128);
    cudaFuncSetAttribute(k_gemm<64>,  cudaFuncAttributeMaxDynamicSharedMemorySize, (int)sh64);

    // graph preprocessing (gemm128 slotted at launch index 3 for profiling)
    k_zero_detect<<<(n + 255) / 256, 256>>>(ei, n);                      // 0
    k_hist<<<(E + 255) / 256, 256>>>(ei, E);                             // 1
    k_scan1<<<ntiles, 1024>>>(n);                                        // 2
    k_gemm<128><<<(n + 127) / 128, 512, sh128>>>(x, W1, p_dis, p_xw, n); // 3
    k_scan23<<<(n + 255) / 256, 256>>>(n, ntiles);                       // 4
    k_scatter<<<(E + 255) / 256, 256>>>(ei, E);                          // 5

    // layer 1 aggregate + relu
    k_agg128<<<(n + 7) / 8, 256>>>(p_xw, b1, p_h, n);                    // 6

    // layer 2
    k_gemm<64><<<(n + 255) / 256, 512, sh64>>>(p_h, W2, p_dis, p_hw, n); // 7
    k_agg64<<<(n + 7) / 8, 256>>>(p_hw, b2, out, n);                     // 8
}

// round 5
// speedup vs baseline: 1.2233x; 1.2233x over previous
#include <cuda_runtime.h>

#define MAXN 50000
#define MAXE 800000
#define FIN  128
#define FHID 128
#define FOUT2 64
#define SCAN_TILE 4096
#define MAXTILES 32

// ---------------- scratch (device globals; no allocation allowed) ----------
__device__ int   g_deg[MAXN];
__device__ int   g_off[MAXN + 1];
__device__ int   g_cur[MAXN];
__device__ float g_dis[MAXN];        // rsqrt(deg+1)
__device__ int   g_srcs[MAXE];
__device__ int   g_is64;
__device__ int   g_tsum[MAXTILES];
__device__ float g_xw[MAXN * FHID];  // dis ⊙ (x @ W1)
__device__ float g_h [MAXN * FHID];
__device__ float g_hw[MAXN * FOUT2]; // dis ⊙ (h @ W2)

// ---------------- zero + dtype detection -----------------------------------
__global__ void k_zero_detect(const void* ei, int n) {
    int i = blockIdx.x * blockDim.x + threadIdx.x;
    if (i < n) { g_deg[i] = 0; g_cur[i] = 0; }
    if (blockIdx.x == 0) {
        const long long* p = (const long long*)ei;
        int tid = threadIdx.x;
        int ok = 1;
        #pragma unroll
        for (int j = 0; j < 8; j++) {
            long long v = p[tid * 8 + j];
            if (v < 0 || v >= (long long)n) ok = 0;
        }
        int all_ok = __syncthreads_and(ok);
        if (tid == 0) g_is64 = all_ok;
    }
}

__device__ __forceinline__ int load_idx(const void* ei, long long pos, int is64) {
    if (is64) return (int)((const long long*)ei)[pos];
    return ((const int*)ei)[pos];
}

__global__ void k_hist(const void* ei, int E) {
    int e = blockIdx.x * blockDim.x + threadIdx.x;
    if (e >= E) return;
    int is64 = g_is64;
    int col = load_idx(ei, (long long)E + e, is64);
    atomicAdd(&g_deg[col], 1);
}

// ---------------- scan phase 1: per-tile exclusive scan + dis ---------------
__global__ void k_scan1(int n) {
    __shared__ int wsum[32];
    int tid  = threadIdx.x;
    int lane = tid & 31, wid = tid >> 5;
    int base = blockIdx.x * SCAN_TILE + tid * 4;

    int v[4];
    #pragma unroll
    for (int j = 0; j < 4; j++) {
        int i = base + j;
        if (i < n) {
            int d = g_deg[i];
            v[j] = d;
            g_dis[i] = rsqrtf((float)(d + 1));
        } else v[j] = 0;
    }
    int s = v[0] + v[1] + v[2] + v[3];

    int inc = s;
    #pragma unroll
    for (int d = 1; d < 32; d <<= 1) {
        int t = __shfl_up_sync(0xffffffffu, inc, d);
        if (lane >= d) inc += t;
    }
    if (lane == 31) wsum[wid] = inc;
    __syncthreads();
    if (wid == 0) {
        int w = wsum[lane];
        #pragma unroll
        for (int d = 1; d < 32; d <<= 1) {
            int t = __shfl_up_sync(0xffffffffu, w, d);
            if (lane >= d) w += t;
        }
        wsum[lane] = w;
    }
    __syncthreads();
    int excl = inc - s + (wid > 0 ? wsum[wid - 1] : 0);
    int run = excl;
    #pragma unroll
    for (int j = 0; j < 4; j++) {
        int i = base + j;
        if (i < n) g_off[i] = run;
        run += v[j];
    }
    if (tid == 0) g_tsum[blockIdx.x] = wsum[31];
}

// ---------------- scan phases 2+3 merged ------------------------------------
__global__ void k_scan23(int n, int ntiles) {
    __shared__ int sh_toff[32];
    int tid = threadIdx.x;
    if (tid < 32) {
        int t = (tid < ntiles) ? g_tsum[tid] : 0;
        int inc = t;
        #pragma unroll
        for (int d = 1; d < 32; d <<= 1) {
            int u = __shfl_up_sync(0xffffffffu, inc, d);
            if (tid >= d) inc += u;
        }
        sh_toff[tid] = inc - t;
        if (tid == 31 && blockIdx.x == 0) g_off[n] = inc;
    }
    __syncthreads();
    int i = blockIdx.x * blockDim.x + tid;
    if (i < n) g_off[i] += sh_toff[i >> 12];
}

__global__ void k_scatter(const void* ei, int E) {
    int e = blockIdx.x * blockDim.x + threadIdx.x;
    if (e >= E) return;
    int is64 = g_is64;
    int row = load_idx(ei, e, is64);
    int col = load_idx(ei, (long long)E + e, is64);
    int pos = g_off[col] + atomicAdd(&g_cur[col], 1);
    g_srcs[pos] = row;
}

// ---------------- GEMM: Y[n,FO] = scale[r] * (X[n,128] @ W[128,FO]) ---------
// Round-2 proven shape: 512 threads; 8 rows x 4 cols per thread; float4 SMEM.
template <int FO>
__global__ void __launch_bounds__(512, 1)
k_gemm(const float* __restrict__ X, const float* __restrict__ W,
       const float* __restrict__ scale, float* __restrict__ Y, int n) {
    constexpr int NT   = 512;
    constexpr int CG   = FO / 4;         // 32 or 16
    constexpr int RG   = NT / CG;        // 16 or 32
    constexpr int RPT  = 8;
    constexpr int ROWS = RG * RPT;       // 128 or 256
    constexpr int SXP4 = 33;             // padded float4 row stride
    extern __shared__ float sh[];
    float4* sW4 = (float4*)sh;                    // 32*FO float4
    float4* sX4 = (float4*)(sh + 128 * FO);       // ROWS * SXP4 float4

    int tid  = threadIdx.x;
    int row0 = blockIdx.x * ROWS;
    const float4* W4g = (const float4*)W;
    const float4* X4g = (const float4*)X;

    for (int i = tid; i < 32 * FO; i += NT) sW4[i] = W4g[i];
    for (int i = tid; i < ROWS * 32; i += NT) {
        int r = i >> 5, c = i & 31;
        int gr = row0 + r;
        sX4[r * SXP4 + c] = (gr < n) ? X4g[gr * 32 + c]
                                     : make_float4(0.f, 0.f, 0.f, 0.f);
    }
    __syncthreads();

    int cg = tid % CG;
    int rb = (tid / CG) * RPT;
    float4 acc[RPT];
    #pragma unroll
    for (int r = 0; r < RPT; r++) acc[r] = make_float4(0.f, 0.f, 0.f, 0.f);

    #pragma unroll 2
    for (int kk = 0; kk < 32; kk++) {
        float4 w0 = sW4[(4 * kk + 0) * CG + cg];
        float4 w1 = sW4[(4 * kk + 1) * CG + cg];
        float4 w2 = sW4[(4 * kk + 2) * CG + cg];
        float4 w3 = sW4[(4 * kk + 3) * CG + cg];
        #pragma unroll
        for (int r = 0; r < RPT; r++) {
            float4 a = sX4[(rb + r) * SXP4 + kk];
            acc[r].x += a.x * w0.x; acc[r].y += a.x * w0.y;
            acc[r].z += a.x * w0.z; acc[r].w += a.x * w0.w;
            acc[r].x += a.y * w1.x; acc[r].y += a.y * w1.y;
            acc[r].z += a.y * w1.z; acc[r].w += a.y * w1.w;
            acc[r].x += a.z * w2.x; acc[r].y += a.z * w2.y;
            acc[r].z += a.z * w2.z; acc[r].w += a.z * w2.w;
            acc[r].x += a.w * w3.x; acc[r].y += a.w * w3.y;
            acc[r].z += a.w * w3.z; acc[r].w += a.w * w3.w;
        }
    }
    float4* Y4 = (float4*)Y;
    #pragma unroll
    for (int r = 0; r < RPT; r++) {
        int gr = row0 + rb + r;
        if (gr < n) {
            float sc = scale[gr];
            float4 o = acc[r];
            o.x *= sc; o.y *= sc; o.z *= sc; o.w *= sc;
            Y4[gr * CG + cg] = o;
        }
    }
}

// ---------------- aggregation: warp per destination node -------------------
// in is pre-scaled by dis: out = di*(sum_{j in in(i)} in[j] + in[i]) + b
__global__ void k_agg128(const float* __restrict__ xw, const float* __restrict__ bias,
                         float* __restrict__ out, int n) {
    int warp = (blockIdx.x * blockDim.x + threadIdx.x) >> 5;
    int lane = threadIdx.x & 31;
    if (warp >= n) return;
    int node = warp;
    int s = g_off[node], e = g_off[node + 1];
    float di = g_dis[node];
    const float4* xw4 = (const float4*)xw;

    float4 acc = xw4[node * 32 + lane];   // self term (pre-scaled)
    int p = s;
    for (; p + 3 < e; p += 4) {
        int s0 = g_srcs[p], s1 = g_srcs[p + 1], s2 = g_srcs[p + 2], s3 = g_srcs[p + 3];
        float4 v0 = xw4[s0 * 32 + lane];
        float4 v1 = xw4[s1 * 32 + lane];
        float4 v2 = xw4[s2 * 32 + lane];
        float4 v3 = xw4[s3 * 32 + lane];
        acc.x += v0.x + v1.x + v2.x + v3.x;
        acc.y += v0.y + v1.y + v2.y + v3.y;
        acc.z += v0.z + v1.z + v2.z + v3.z;
        acc.w += v0.w + v1.w + v2.w + v3.w;
    }
    for (; p < e; p++) {
        int s0 = g_srcs[p];
        float4 v0 = xw4[s0 * 32 + lane];
        acc.x += v0.x; acc.y += v0.y; acc.z += v0.z; acc.w += v0.w;
    }
    float4 bb = ((const float4*)bias)[lane];
    acc.x = fmaxf(di * acc.x + bb.x, 0.f);
    acc.y = fmaxf(di * acc.y + bb.y, 0.f);
    acc.z = fmaxf(di * acc.z + bb.z, 0.f);
    acc.w = fmaxf(di * acc.w + bb.w, 0.f);
    ((float4*)out)[node * 32 + lane] = acc;
}

__global__ void k_agg64(const float* __restrict__ hw, const float* __restrict__ bias,
                        float* __restrict__ out, int n) {
    int warp = (blockIdx.x * blockDim.x + threadIdx.x) >> 5;
    int lane = threadIdx.x & 31;
    if (warp >= n) return;
    int node = warp;
    int s = g_off[node], e = g_off[node + 1];
    float di = g_dis[node];
    const float2* hw2 = (const float2*)hw;

    float2 acc = hw2[node * 32 + lane];   // self term
    int p = s;
    for (; p + 3 < e; p += 4) {
        int s0 = g_srcs[p], s1 = g_srcs[p + 1], s2 = g_srcs[p + 2], s3 = g_srcs[p + 3];
        float2 v0 = hw2[s0 * 32 + lane];
        float2 v1 = hw2[s1 * 32 + lane];
        float2 v2 = hw2[s2 * 32 + lane];
        float2 v3 = hw2[s3 * 32 + lane];
        acc.x += v0.x + v1.x + v2.x + v3.x;
        acc.y += v0.y + v1.y + v2.y + v3.y;
    }
    for (; p < e; p++) {
        int s0 = g_srcs[p];
        float2 v0 = hw2[s0 * 32 + lane];
        acc.x += v0.x; acc.y += v0.y;
    }
    float2 bb = ((const float2*)bias)[lane];
    acc.x = di * acc.x + bb.x;
    acc.y = di * acc.y + bb.y;
    ((float2*)out)[node * 32 + lane] = acc;
}

// ---------------- launch ----------------------------------------------------
extern "C" void kernel_launch(void* const* d_in, const int* in_sizes, int n_in,
                              void* d_out, int out_size) {
    const float* x  = (const float*)d_in[0];
    const void*  ei = d_in[1];
    const float* W1 = (const float*)d_in[2];
    const float* b1 = (const float*)d_in[3];
    const float* W2 = (const float*)d_in[4];
    const float* b2 = (const float*)d_in[5];
    float* out = (float*)d_out;

    int n = in_sizes[0] / FIN;
    int E = in_sizes[1] / 2;
    if (n > MAXN) n = MAXN;
    if (E > MAXE) E = MAXE;
    int ntiles = (n + SCAN_TILE - 1) / SCAN_TILE;

    float *p_xw, *p_h, *p_hw, *p_dis;
    cudaGetSymbolAddress((void**)&p_xw,  g_xw);
    cudaGetSymbolAddress((void**)&p_h,   g_h);
    cudaGetSymbolAddress((void**)&p_hw,  g_hw);
    cudaGetSymbolAddress((void**)&p_dis, g_dis);

    size_t sh128 = (size_t)(128 * 128 + 128 * 132) * sizeof(float);   // 133120
    size_t sh64  = (size_t)(128 * 64  + 256 * 132) * sizeof(float);   // 167936
    cudaFuncSetAttribute(k_gemm<128>, cudaFuncAttributeMaxDynamicSharedMemorySize, (int)sh128);
    cudaFuncSetAttribute(k_gemm<64>,  cudaFuncAttributeMaxDynamicSharedMemorySize, (int)sh64);

    // graph preprocessing (gemm128 slotted at launch index 3 for profiling)
    k_zero_detect<<<(n + 255) / 256, 256>>>(ei, n);                      // 0
    k_hist<<<(E + 255) / 256, 256>>>(ei, E);                             // 1
    k_scan1<<<ntiles, 1024>>>(n);                                        // 2
    k_gemm<128><<<(n + 127) / 128, 512, sh128>>>(x, W1, p_dis, p_xw, n); // 3
    k_scan23<<<(n + 255) / 256, 256>>>(n, ntiles);                       // 4
    k_scatter<<<(E + 255) / 256, 256>>>(ei, E);                          // 5

    // layer 1 aggregate + relu
    k_agg128<<<(n + 7) / 8, 256>>>(p_xw, b1, p_h, n);                    // 6

    // layer 2
    k_gemm<64><<<(n + 255) / 256, 512, sh64>>>(p_h, W2, p_dis, p_hw, n); // 7
    k_agg64<<<(n + 7) / 8, 256>>>(p_hw, b2, out, n);                     // 8
}

// round 7
// speedup vs baseline: 1.4896x; 1.2177x over previous
#include <cuda_runtime.h>
#include <cuda_bf16.h>
#include <cstdint>

#define MAXN 50000
#define MAXE 800000
#define FIN  128
#define FHID 128
#define FOUT2 64
#define SCAN_TILE 4096
#define MAXTILES 32

// ---------------- scratch (device globals; no allocation allowed) ----------
__device__ int   g_deg[MAXN];
__device__ int   g_off[MAXN + 1];
__device__ int   g_cur[MAXN];
__device__ float g_dis[MAXN];        // rsqrt(deg+1)
__device__ int   g_srcs[MAXE];
__device__ int   g_is64;
__device__ int   g_tsum[MAXTILES];
__device__ float g_xw[MAXN * FHID];  // dis ⊙ (x @ W1)
__device__ float g_h [MAXN * FHID];
__device__ float g_hw[MAXN * FOUT2]; // dis ⊙ (h @ W2)
// W transposed ([n][k]) and split to bf16 hi/lo
__device__ __nv_bfloat16 g_Wt1hi[FHID * FIN];
__device__ __nv_bfloat16 g_Wt1lo[FHID * FIN];
__device__ __nv_bfloat16 g_Wt2hi[FOUT2 * FHID];
__device__ __nv_bfloat16 g_Wt2lo[FOUT2 * FHID];

// ---------------- helpers ----------------------------------------------------
__device__ __forceinline__ int load_idx(const void* ei, long long pos, int is64) {
    if (is64) return (int)((const long long*)ei)[pos];
    return ((const int*)ei)[pos];
}

__device__ __forceinline__ void mma_bf16(float* d, const uint32_t* a,
                                         uint32_t b0, uint32_t b1) {
    asm volatile(
        "mma.sync.aligned.m16n8k16.row.col.f32.bf16.bf16.f32 "
        "{%0,%1,%2,%3}, {%4,%5,%6,%7}, {%8,%9}, {%0,%1,%2,%3};"
        : "+f"(d[0]), "+f"(d[1]), "+f"(d[2]), "+f"(d[3])
        : "r"(a[0]), "r"(a[1]), "r"(a[2]), "r"(a[3]), "r"(b0), "r"(b1));
}

// ---------------- preproc: zero + detect + W -> Wt bf16 hi/lo ---------------
__global__ void k_pre(const void* ei, const float* __restrict__ W1,
                      const float* __restrict__ W2, int n, int nbn) {
    int b = blockIdx.x, tid = threadIdx.x;
    if (b < nbn) {
        int i = b * 256 + tid;
        if (i < n) { g_deg[i] = 0; g_cur[i] = 0; }
        if (b == 0) {
            const long long* p = (const long long*)ei;
            int ok = 1;
            #pragma unroll
            for (int j = 0; j < 8; j++) {
                long long v = p[tid * 8 + j];
                if (v < 0 || v >= (long long)n) ok = 0;
            }
            int all_ok = __syncthreads_and(ok);
            if (tid == 0) g_is64 = all_ok;
        }
    } else if (b < nbn + 64) {            // W1: 16384 elems, [k=128][n=128]
        int e = (b - nbn) * 256 + tid;
        int k = e >> 7, nn = e & 127;
        float w = W1[e];
        __nv_bfloat16 h = __float2bfloat16_rn(w);
        __nv_bfloat16 l = __float2bfloat16_rn(w - __bfloat162float(h));
        g_Wt1hi[nn * 128 + k] = h;
        g_Wt1lo[nn * 128 + k] = l;
    } else {                               // W2: 8192 elems, [k=128][n=64]
        int e = (b - nbn - 64) * 256 + tid;
        int k = e >> 6, nn = e & 63;
        float w = W2[e];
        __nv_bfloat16 h = __float2bfloat16_rn(w);
        __nv_bfloat16 l = __float2bfloat16_rn(w - __bfloat162float(h));
        g_Wt2hi[nn * 128 + k] = h;
        g_Wt2lo[nn * 128 + k] = l;
    }
}

__global__ void k_hist(const void* ei, int E) {
    int e = blockIdx.x * blockDim.x + threadIdx.x;
    if (e >= E) return;
    int is64 = g_is64;
    int col = load_idx(ei, (long long)E + e, is64);
    atomicAdd(&g_deg[col], 1);
}

// ---------------- scan phase 1 ----------------------------------------------
__global__ void k_scan1(int n) {
    __shared__ int wsum[32];
    int tid  = threadIdx.x;
    int lane = tid & 31, wid = tid >> 5;
    int base = blockIdx.x * SCAN_TILE + tid * 4;

    int v[4];
    #pragma unroll
    for (int j = 0; j < 4; j++) {
        int i = base + j;
        if (i < n) {
            int d = g_deg[i];
            v[j] = d;
            g_dis[i] = rsqrtf((float)(d + 1));
        } else v[j] = 0;
    }
    int s = v[0] + v[1] + v[2] + v[3];

    int inc = s;
    #pragma unroll
    for (int d = 1; d < 32; d <<= 1) {
        int t = __shfl_up_sync(0xffffffffu, inc, d);
        if (lane >= d) inc += t;
    }
    if (lane == 31) wsum[wid] = inc;
    __syncthreads();
    if (wid == 0) {
        int w = wsum[lane];
        #pragma unroll
        for (int d = 1; d < 32; d <<= 1) {
            int t = __shfl_up_sync(0xffffffffu, w, d);
            if (lane >= d) w += t;
        }
        wsum[lane] = w;
    }
    __syncthreads();
    int excl = inc - s + (wid > 0 ? wsum[wid - 1] : 0);
    int run = excl;
    #pragma unroll
    for (int j = 0; j < 4; j++) {
        int i = base + j;
        if (i < n) g_off[i] = run;
        run += v[j];
    }
    if (tid == 0) g_tsum[blockIdx.x] = wsum[31];
}

// ---------------- scan phases 2+3 merged ------------------------------------
__global__ void k_scan23(int n, int ntiles) {
    __shared__ int sh_toff[32];
    int tid = threadIdx.x;
    if (tid < 32) {
        int t = (tid < ntiles) ? g_tsum[tid] : 0;
        int inc = t;
        #pragma unroll
        for (int d = 1; d < 32; d <<= 1) {
            int u = __shfl_up_sync(0xffffffffu, inc, d);
            if (tid >= d) inc += u;
        }
        sh_toff[tid] = inc - t;
        if (tid == 31 && blockIdx.x == 0) g_off[n] = inc;
    }
    __syncthreads();
    int i = blockIdx.x * blockDim.x + tid;
    if (i < n) g_off[i] += sh_toff[i >> 12];
}

__global__ void k_scatter(const void* ei, int E) {
    int e = blockIdx.x * blockDim.x + threadIdx.x;
    if (e >= E) return;
    int is64 = g_is64;
    int row = load_idx(ei, e, is64);
    int col = load_idx(ei, (long long)E + e, is64);
    int pos = g_off[col] + atomicAdd(&g_cur[col], 1);
    g_srcs[pos] = row;
}

// ---------------- HMMA GEMM: Y = scale[r] * (X[n,128] @ W[128,FO]) ----------
// 3-term bf16 split; mma.sync m16n8k16. Block: 256 thr / 8 warps; M-tile 128.
// Warp grid 4(row)x2(col): warp handles 32 rows x FO/2 cols.
template <int FO>
__global__ void __launch_bounds__(256, 1)
k_gemm_mma(const float* __restrict__ X, const __nv_bfloat16* __restrict__ Whi,
           const __nv_bfloat16* __restrict__ Wlo, const float* __restrict__ scale,
           float* __restrict__ Y, int n) {
    constexpr int NTW = FO / 16;          // n-tiles per warp (8 or 4)
    constexpr int SAS = 136;              // padded bf16 row stride (17 x 16B)
    extern __shared__ char smem[];
    __nv_bfloat16* sAhi = (__nv_bfloat16*)smem;
    __nv_bfloat16* sAlo = sAhi + 128 * SAS;
    __nv_bfloat16* sBhi = sAlo + 128 * SAS;
    __nv_bfloat16* sBlo = sBhi + FO * SAS;

    int tid = threadIdx.x;
    int row0 = blockIdx.x * 128;

    // stage X tile -> bf16 hi/lo (zero-padded out of range)
    const float4* X4 = (const float4*)X;
    for (int i = tid; i < 128 * 32; i += 256) {
        int r = i >> 5, c = i & 31;
        int gr = row0 + r;
        float4 f = (gr < n) ? X4[(size_t)gr * 32 + c]
                            : make_float4(0.f, 0.f, 0.f, 0.f);
        __nv_bfloat16 hx = __float2bfloat16_rn(f.x);
        __nv_bfloat16 hy = __float2bfloat16_rn(f.y);
        __nv_bfloat16 hz = __float2bfloat16_rn(f.z);
        __nv_bfloat16 hw = __float2bfloat16_rn(f.w);
        __nv_bfloat162 h0 = __halves2bfloat162(hx, hy);
        __nv_bfloat162 h1 = __halves2bfloat162(hz, hw);
        __nv_bfloat162 l0 = __floats2bfloat162_rn(f.x - __bfloat162float(hx),
                                                  f.y - __bfloat162float(hy));
        __nv_bfloat162 l1 = __floats2bfloat162_rn(f.z - __bfloat162float(hz),
                                                  f.w - __bfloat162float(hw));
        uint32_t* dh = (uint32_t*)(sAhi + r * SAS + c * 4);
        uint32_t* dl = (uint32_t*)(sAlo + r * SAS + c * 4);
        dh[0] = *(uint32_t*)&h0; dh[1] = *(uint32_t*)&h1;
        dl[0] = *(uint32_t*)&l0; dl[1] = *(uint32_t*)&l1;
    }
    // stage Wt (pre-split) -> SMEM, padded rows
    const uint4* Wh4 = (const uint4*)Whi;
    const uint4* Wl4 = (const uint4*)Wlo;
    for (int i = tid; i < FO * 16; i += 256) {
        int r = i >> 4, c = i & 15;
        *(uint4*)((char*)sBhi + r * 272 + c * 16) = Wh4[r * 16 + c];
        *(uint4*)((char*)sBlo + r * 272 + c * 16) = Wl4[r * 16 + c];
    }
    __syncthreads();

    int wid = tid >> 5, lane = tid & 31;
    int wr = wid >> 1, wc = wid & 1;
    int g = lane >> 2, t = lane & 3;

    float acc[2][NTW][4];
    #pragma unroll
    for (int rg = 0; rg < 2; rg++)
        #pragma unroll
        for (int nt = 0; nt < NTW; nt++)
            #pragma unroll
            for (int c = 0; c < 4; c++) acc[rg][nt][c] = 0.f;

    #pragma unroll
    for (int k0 = 0; k0 < 128; k0 += 16) {
        uint32_t ahi[2][4], alo[2][4];
        #pragma unroll
        for (int rg = 0; rg < 2; rg++) {
            const __nv_bfloat16* ph = sAhi + (wr * 32 + rg * 16 + g) * SAS + k0 + 2 * t;
            const __nv_bfloat16* pl = sAlo + (wr * 32 + rg * 16 + g) * SAS + k0 + 2 * t;
            ahi[rg][0] = *(const uint32_t*)ph;
            ahi[rg][1] = *(const uint32_t*)(ph + 8 * SAS);
            ahi[rg][2] = *(const uint32_t*)(ph + 8);
            ahi[rg][3] = *(const uint32_t*)(ph + 8 * SAS + 8);
            alo[rg][0] = *(const uint32_t*)pl;
            alo[rg][1] = *(const uint32_t*)(pl + 8 * SAS);
            alo[rg][2] = *(const uint32_t*)(pl + 8);
            alo[rg][3] = *(const uint32_t*)(pl + 8 * SAS + 8);
        }
        #pragma unroll
        for (int nt = 0; nt < NTW; nt++) {
            int ncol = wc * (NTW * 8) + nt * 8 + g;
            const __nv_bfloat16* pbh = sBhi + ncol * SAS + k0 + 2 * t;
            const __nv_bfloat16* pbl = sBlo + ncol * SAS + k0 + 2 * t;
            uint32_t bh0 = *(const uint32_t*)pbh;
            uint32_t bh1 = *(const uint32_t*)(pbh + 8);
            uint32_t bl0 = *(const uint32_t*)pbl;
            uint32_t bl1 = *(const uint32_t*)(pbl + 8);
            #pragma unroll
            for (int rg = 0; rg < 2; rg++) {
                mma_bf16(acc[rg][nt], ahi[rg], bh0, bh1);
                mma_bf16(acc[rg][nt], ahi[rg], bl0, bl1);
                mma_bf16(acc[rg][nt], alo[rg], bh0, bh1);
            }
        }
    }

    // epilogue: d0,d1 -> (row, 2t), d2,d3 -> (row+8, 2t); scale per row
    #pragma unroll
    for (int rg = 0; rg < 2; rg++) {
        int r_lo = row0 + wr * 32 + rg * 16 + g;
        int r_hi = r_lo + 8;
        float s0 = (r_lo < n) ? scale[r_lo] : 0.f;
        float s1 = (r_hi < n) ? scale[r_hi] : 0.f;
        #pragma unroll
        for (int nt = 0; nt < NTW; nt++) {
            int col = wc * (NTW * 8) + nt * 8 + 2 * t;
            if (r_lo < n) {
                float2 o = make_float2(acc[rg][nt][0] * s0, acc[rg][nt][1] * s0);
                *(float2*)(Y + (size_t)r_lo * FO + col) = o;
            }
            if (r_hi < n) {
                float2 o = make_float2(acc[rg][nt][2] * s1, acc[rg][nt][3] * s1);
                *(float2*)(Y + (size_t)r_hi * FO + col) = o;
            }
        }
    }
}

// ---------------- aggregation: warp per destination node -------------------
__global__ void k_agg128(const float* __restrict__ xw, const float* __restrict__ bias,
                         float* __restrict__ out, int n) {
    int warp = (blockIdx.x * blockDim.x + threadIdx.x) >> 5;
    int lane = threadIdx.x & 31;
    if (warp >= n) return;
    int node = warp;
    int s = g_off[node], e = g_off[node + 1];
    float di = g_dis[node];
    const float4* xw4 = (const float4*)xw;

    float4 acc = xw4[node * 32 + lane];
    int p = s;
    for (; p + 3 < e; p += 4) {
        int s0 = g_srcs[p], s1 = g_srcs[p + 1], s2 = g_srcs[p + 2], s3 = g_srcs[p + 3];
        float4 v0 = xw4[s0 * 32 + lane];
        float4 v1 = xw4[s1 * 32 + lane];
        float4 v2 = xw4[s2 * 32 + lane];
        float4 v3 = xw4[s3 * 32 + lane];
        acc.x += v0.x + v1.x + v2.x + v3.x;
        acc.y += v0.y + v1.y + v2.y + v3.y;
        acc.z += v0.z + v1.z + v2.z + v3.z;
        acc.w += v0.w + v1.w + v2.w + v3.w;
    }
    for (; p < e; p++) {
        int s0 = g_srcs[p];
        float4 v0 = xw4[s0 * 32 + lane];
        acc.x += v0.x; acc.y += v0.y; acc.z += v0.z; acc.w += v0.w;
    }
    float4 bb = ((const float4*)bias)[lane];
    acc.x = fmaxf(di * acc.x + bb.x, 0.f);
    acc.y = fmaxf(di * acc.y + bb.y, 0.f);
    acc.z = fmaxf(di * acc.z + bb.z, 0.f);
    acc.w = fmaxf(di * acc.w + bb.w, 0.f);
    ((float4*)out)[node * 32 + lane] = acc;
}

__global__ void k_agg64(const float* __restrict__ hw, const float* __restrict__ bias,
                        float* __restrict__ out, int n) {
    int warp = (blockIdx.x * blockDim.x + threadIdx.x) >> 5;
    int lane = threadIdx.x & 31;
    if (warp >= n) return;
    int node = warp;
    int s = g_off[node], e = g_off[node + 1];
    float di = g_dis[node];
    const float2* hw2 = (const float2*)hw;

    float2 acc = hw2[node * 32 + lane];
    int p = s;
    for (; p + 3 < e; p += 4) {
        int s0 = g_srcs[p], s1 = g_srcs[p + 1], s2 = g_srcs[p + 2], s3 = g_srcs[p + 3];
        float2 v0 = hw2[s0 * 32 + lane];
        float2 v1 = hw2[s1 * 32 + lane];
        float2 v2 = hw2[s2 * 32 + lane];
        float2 v3 = hw2[s3 * 32 + lane];
        acc.x += v0.x + v1.x + v2.x + v3.x;
        acc.y += v0.y + v1.y + v2.y + v3.y;
    }
    for (; p < e; p++) {
        int s0 = g_srcs[p];
        float2 v0 = hw2[s0 * 32 + lane];
        acc.x += v0.x; acc.y += v0.y;
    }
    float2 bb = ((const float2*)bias)[lane];
    acc.x = di * acc.x + bb.x;
    acc.y = di * acc.y + bb.y;
    ((float2*)out)[node * 32 + lane] = acc;
}

// ---------------- launch ----------------------------------------------------
extern "C" void kernel_launch(void* const* d_in, const int* in_sizes, int n_in,
                              void* d_out, int out_size) {
    const float* x  = (const float*)d_in[0];
    const void*  ei = d_in[1];
    const float* W1 = (const float*)d_in[2];
    const float* b1 = (const float*)d_in[3];
    const float* W2 = (const float*)d_in[4];
    const float* b2 = (const float*)d_in[5];
    float* out = (float*)d_out;

    int n = in_sizes[0] / FIN;
    int E = in_sizes[1] / 2;
    if (n > MAXN) n = MAXN;
    if (E > MAXE) E = MAXE;
    int ntiles = (n + SCAN_TILE - 1) / SCAN_TILE;
    int nbn = (n + 255) / 256;

    float *p_xw, *p_h, *p_hw, *p_dis;
    __nv_bfloat16 *p_w1h, *p_w1l, *p_w2h, *p_w2l;
    cudaGetSymbolAddress((void**)&p_xw,  g_xw);
    cudaGetSymbolAddress((void**)&p_h,   g_h);
    cudaGetSymbolAddress((void**)&p_hw,  g_hw);
    cudaGetSymbolAddress((void**)&p_dis, g_dis);
    cudaGetSymbolAddress((void**)&p_w1h, g_Wt1hi);
    cudaGetSymbolAddress((void**)&p_w1l, g_Wt1lo);
    cudaGetSymbolAddress((void**)&p_w2h, g_Wt2hi);
    cudaGetSymbolAddress((void**)&p_w2l, g_Wt2lo);

    // dynamic SMEM: (2*128 + 2*FO) rows * 136 bf16 * 2B
    size_t shg128 = (size_t)(2 * 128 + 2 * 128) * 136 * 2;  // 139264
    size_t shg64  = (size_t)(2 * 128 + 2 * 64)  * 136 * 2;  // 104448
    cudaFuncSetAttribute(k_gemm_mma<128>, cudaFuncAttributeMaxDynamicSharedMemorySize, (int)shg128);
    cudaFuncSetAttribute(k_gemm_mma<64>,  cudaFuncAttributeMaxDynamicSharedMemorySize, (int)shg64);

    int gemm_blocks = (n + 127) / 128;

    // preprocessing + layer pipeline (gemm at launch index 3 for ncu)
    k_pre<<<nbn + 96, 256>>>(ei, W1, W2, n, nbn);                              // 0
    k_hist<<<(E + 255) / 256, 256>>>(ei, E);                                   // 1
    k_scan1<<<ntiles, 1024>>>(n);                                              // 2
    k_gemm_mma<128><<<gemm_blocks, 256, shg128>>>(x, p_w1h, p_w1l, p_dis, p_xw, n); // 3
    k_scan23<<<(n + 255) / 256, 256>>>(n, ntiles);                             // 4
    k_scatter<<<(E + 255) / 256, 256>>>(ei, E);                                // 5

    k_agg128<<<(n + 7) / 8, 256>>>(p_xw, b1, p_h, n);                          // 6
    k_gemm_mma<64><<<gemm_blocks, 256, shg64>>>(p_h, p_w2h, p_w2l, p_dis, p_hw, n); // 7
    k_agg64<<<(n + 7) / 8, 256>>>(p_hw, b2, out, n);                           // 8
}

// round 8
// speedup vs baseline: 1.4902x; 1.0005x over previous
#include <cuda_runtime.h>
#include <cuda_bf16.h>
#include <cstdint>

#define MAXN 50000
#define MAXE 800000
#define FIN  128
#define FHID 128
#define FOUT2 64
#define SCAN_TILE 4096
#define MAXTILES 32

// ---------------- scratch (device globals; no allocation allowed) ----------
__device__ int   g_deg[MAXN];
__device__ int   g_off[MAXN + 1];
__device__ int   g_cur[MAXN];
__device__ float g_dis[MAXN];        // rsqrt(deg+1)
__device__ int   g_srcs[MAXE];
__device__ int   g_is64;
__device__ int   g_tsum[MAXTILES];
__device__ float g_xw[MAXN * FHID];  // dis ⊙ (x @ W1)
__device__ float g_h [MAXN * FHID];
__device__ float g_hw[MAXN * FOUT2]; // dis ⊙ (h @ W2)
// W transposed ([n][k]), bf16 hi/lo packed as uint2 {hi_pair, lo_pair} per k-pair
__device__ uint2 g_Wp1[FHID * FIN / 2];   // 64KB
__device__ uint2 g_Wp2[FOUT2 * FHID / 2]; // 32KB

// ---------------- helpers ----------------------------------------------------
__device__ __forceinline__ int load_idx(const void* ei, long long pos, int is64) {
    if (is64) return (int)((const long long*)ei)[pos];
    return ((const int*)ei)[pos];
}

__device__ __forceinline__ void mma_bf16(float* d, const uint32_t* a,
                                         uint32_t b0, uint32_t b1) {
    asm volatile(
        "mma.sync.aligned.m16n8k16.row.col.f32.bf16.bf16.f32 "
        "{%0,%1,%2,%3}, {%4,%5,%6,%7}, {%8,%9}, {%0,%1,%2,%3};"
        : "+f"(d[0]), "+f"(d[1]), "+f"(d[2]), "+f"(d[3])
        : "r"(a[0]), "r"(a[1]), "r"(a[2]), "r"(a[3]), "r"(b0), "r"(b1));
}

// ---------------- preproc: zero + detect + W -> packed Wt bf16 hi/lo --------
__global__ void k_pre(const void* ei, const float* __restrict__ W1,
                      const float* __restrict__ W2, int n, int nbn) {
    int b = blockIdx.x, tid = threadIdx.x;
    if (b < nbn) {
        int i = b * 256 + tid;
        if (i < n) { g_deg[i] = 0; g_cur[i] = 0; }
        if (b == 0) {
            const long long* p = (const long long*)ei;
            int ok = 1;
            #pragma unroll
            for (int j = 0; j < 8; j++) {
                long long v = p[tid * 8 + j];
                if (v < 0 || v >= (long long)n) ok = 0;
            }
            int all_ok = __syncthreads_and(ok);
            if (tid == 0) g_is64 = all_ok;
        }
    } else if (b < nbn + 64) {            // W1: 16384 elems, [k=128][n=128]
        int e = (b - nbn) * 256 + tid;
        int k = e >> 7, nn = e & 127;
        float w = W1[e];
        __nv_bfloat16 h = __float2bfloat16_rn(w);
        __nv_bfloat16 l = __float2bfloat16_rn(w - __bfloat162float(h));
        unsigned char* base = (unsigned char*)g_Wp1 + (nn * 64 + (k >> 1)) * 8;
        *(__nv_bfloat16*)(base + (k & 1) * 2)     = h;
        *(__nv_bfloat16*)(base + 4 + (k & 1) * 2) = l;
    } else {                               // W2: 8192 elems, [k=128][n=64]
        int e = (b - nbn - 64) * 256 + tid;
        int k = e >> 6, nn = e & 63;
        float w = W2[e];
        __nv_bfloat16 h = __float2bfloat16_rn(w);
        __nv_bfloat16 l = __float2bfloat16_rn(w - __bfloat162float(h));
        unsigned char* base = (unsigned char*)g_Wp2 + (nn * 64 + (k >> 1)) * 8;
        *(__nv_bfloat16*)(base + (k & 1) * 2)     = h;
        *(__nv_bfloat16*)(base + 4 + (k & 1) * 2) = l;
    }
}

__global__ void k_hist(const void* ei, int E) {
    int e = blockIdx.x * blockDim.x + threadIdx.x;
    if (e >= E) return;
    int is64 = g_is64;
    int col = load_idx(ei, (long long)E + e, is64);
    atomicAdd(&g_deg[col], 1);
}

// ---------------- scan phase 1 ----------------------------------------------
__global__ void k_scan1(int n) {
    __shared__ int wsum[32];
    int tid  = threadIdx.x;
    int lane = tid & 31, wid = tid >> 5;
    int base = blockIdx.x * SCAN_TILE + tid * 4;

    int v[4];
    #pragma unroll
    for (int j = 0; j < 4; j++) {
        int i = base + j;
        if (i < n) {
            int d = g_deg[i];
            v[j] = d;
            g_dis[i] = rsqrtf((float)(d + 1));
        } else v[j] = 0;
    }
    int s = v[0] + v[1] + v[2] + v[3];

    int inc = s;
    #pragma unroll
    for (int d = 1; d < 32; d <<= 1) {
        int t = __shfl_up_sync(0xffffffffu, inc, d);
        if (lane >= d) inc += t;
    }
    if (lane == 31) wsum[wid] = inc;
    __syncthreads();
    if (wid == 0) {
        int w = wsum[lane];
        #pragma unroll
        for (int d = 1; d < 32; d <<= 1) {
            int t = __shfl_up_sync(0xffffffffu, w, d);
            if (lane >= d) w += t;
        }
        wsum[lane] = w;
    }
    __syncthreads();
    int excl = inc - s + (wid > 0 ? wsum[wid - 1] : 0);
    int run = excl;
    #pragma unroll
    for (int j = 0; j < 4; j++) {
        int i = base + j;
        if (i < n) g_off[i] = run;
        run += v[j];
    }
    if (tid == 0) g_tsum[blockIdx.x] = wsum[31];
}

// ---------------- scan phases 2+3 merged ------------------------------------
__global__ void k_scan23(int n, int ntiles) {
    __shared__ int sh_toff[32];
    int tid = threadIdx.x;
    if (tid < 32) {
        int t = (tid < ntiles) ? g_tsum[tid] : 0;
        int inc = t;
        #pragma unroll
        for (int d = 1; d < 32; d <<= 1) {
            int u = __shfl_up_sync(0xffffffffu, inc, d);
            if (tid >= d) inc += u;
        }
        sh_toff[tid] = inc - t;
        if (tid == 31 && blockIdx.x == 0) g_off[n] = inc;
    }
    __syncthreads();
    int i = blockIdx.x * blockDim.x + tid;
    if (i < n) g_off[i] += sh_toff[i >> 12];
}

__global__ void k_scatter(const void* ei, int E) {
    int e = blockIdx.x * blockDim.x + threadIdx.x;
    if (e >= E) return;
    int is64 = g_is64;
    int row = load_idx(ei, e, is64);
    int col = load_idx(ei, (long long)E + e, is64);
    int pos = g_off[col] + atomicAdd(&g_cur[col], 1);
    g_srcs[pos] = row;
}

// ---------------- HMMA GEMM: Y = scale[r] * (X[n,128] @ W[128,FO]) ----------
// 3-term bf16 split; mma.sync m16n8k16. Block: 256 thr / 8 warps; M-tile 128.
// A (X tile) hi/lo in SMEM; B read directly from global packed uint2 (L1-hot).
template <int FO>
__global__ void __launch_bounds__(256, 2)
k_gemm_mma(const float* __restrict__ X, const uint2* __restrict__ Wp,
           const float* __restrict__ scale, float* __restrict__ Y, int n) {
    constexpr int NTW = FO / 16;          // n-tiles per warp (8 or 4)
    constexpr int SAS = 136;              // padded bf16 row stride (17 x 16B)
    extern __shared__ char smem[];
    __nv_bfloat16* sAhi = (__nv_bfloat16*)smem;
    __nv_bfloat16* sAlo = sAhi + 128 * SAS;

    int tid = threadIdx.x;
    int row0 = blockIdx.x * 128;

    // stage X tile -> bf16 hi/lo (zero-padded out of range)
    const float4* X4 = (const float4*)X;
    for (int i = tid; i < 128 * 32; i += 256) {
        int r = i >> 5, c = i & 31;
        int gr = row0 + r;
        float4 f = (gr < n) ? X4[(size_t)gr * 32 + c]
                            : make_float4(0.f, 0.f, 0.f, 0.f);
        __nv_bfloat16 hx = __float2bfloat16_rn(f.x);
        __nv_bfloat16 hy = __float2bfloat16_rn(f.y);
        __nv_bfloat16 hz = __float2bfloat16_rn(f.z);
        __nv_bfloat16 hw = __float2bfloat16_rn(f.w);
        __nv_bfloat162 h0 = __halves2bfloat162(hx, hy);
        __nv_bfloat162 h1 = __halves2bfloat162(hz, hw);
        __nv_bfloat162 l0 = __floats2bfloat162_rn(f.x - __bfloat162float(hx),
                                                  f.y - __bfloat162float(hy));
        __nv_bfloat162 l1 = __floats2bfloat162_rn(f.z - __bfloat162float(hz),
                                                  f.w - __bfloat162float(hw));
        uint32_t* dh = (uint32_t*)(sAhi + r * SAS + c * 4);
        uint32_t* dl = (uint32_t*)(sAlo + r * SAS + c * 4);
        dh[0] = *(uint32_t*)&h0; dh[1] = *(uint32_t*)&h1;
        dl[0] = *(uint32_t*)&l0; dl[1] = *(uint32_t*)&l1;
    }
    __syncthreads();

    int wid = tid >> 5, lane = tid & 31;
    int wr = wid >> 1, wc = wid & 1;
    int g = lane >> 2, t = lane & 3;

    float acc[2][NTW][4];
    #pragma unroll
    for (int rg = 0; rg < 2; rg++)
        #pragma unroll
        for (int nt = 0; nt < NTW; nt++)
            #pragma unroll
            for (int c = 0; c < 4; c++) acc[rg][nt][c] = 0.f;

    #pragma unroll
    for (int k0 = 0; k0 < 128; k0 += 16) {
        uint32_t ahi[2][4], alo[2][4];
        #pragma unroll
        for (int rg = 0; rg < 2; rg++) {
            const __nv_bfloat16* ph = sAhi + (wr * 32 + rg * 16 + g) * SAS + k0 + 2 * t;
            const __nv_bfloat16* pl = sAlo + (wr * 32 + rg * 16 + g) * SAS + k0 + 2 * t;
            ahi[rg][0] = *(const uint32_t*)ph;
            ahi[rg][1] = *(const uint32_t*)(ph + 8 * SAS);
            ahi[rg][2] = *(const uint32_t*)(ph + 8);
            ahi[rg][3] = *(const uint32_t*)(ph + 8 * SAS + 8);
            alo[rg][0] = *(const uint32_t*)pl;
            alo[rg][1] = *(const uint32_t*)(pl + 8 * SAS);
            alo[rg][2] = *(const uint32_t*)(pl + 8);
            alo[rg][3] = *(const uint32_t*)(pl + 8 * SAS + 8);
        }
        #pragma unroll
        for (int nt = 0; nt < NTW; nt++) {
            int ncol = wc * (NTW * 8) + nt * 8 + g;
            const uint2* bp = Wp + ncol * 64 + (k0 >> 1) + t;
            uint2 b0 = __ldg(bp);       // {hi pair, lo pair} at k0+2t
            uint2 b1 = __ldg(bp + 4);   // {hi pair, lo pair} at k0+2t+8
            #pragma unroll
            for (int rg = 0; rg < 2; rg++) {
                mma_bf16(acc[rg][nt], ahi[rg], b0.x, b1.x);
                mma_bf16(acc[rg][nt], ahi[rg], b0.y, b1.y);
                mma_bf16(acc[rg][nt], alo[rg], b0.x, b1.x);
            }
        }
    }

    // epilogue: d0,d1 -> (row, 2t), d2,d3 -> (row+8, 2t); scale per row
    #pragma unroll
    for (int rg = 0; rg < 2; rg++) {
        int r_lo = row0 + wr * 32 + rg * 16 + g;
        int r_hi = r_lo + 8;
        float s0 = (r_lo < n) ? scale[r_lo] : 0.f;
        float s1 = (r_hi < n) ? scale[r_hi] : 0.f;
        #pragma unroll
        for (int nt = 0; nt < NTW; nt++) {
            int col = wc * (NTW * 8) + nt * 8 + 2 * t;
            if (r_lo < n) {
                float2 o = make_float2(acc[rg][nt][0] * s0, acc[rg][nt][1] * s0);
                *(float2*)(Y + (size_t)r_lo * FO + col) = o;
            }
            if (r_hi < n) {
                float2 o = make_float2(acc[rg][nt][2] * s1, acc[rg][nt][3] * s1);
                *(float2*)(Y + (size_t)r_hi * FO + col) = o;
            }
        }
    }
}

// ---------------- aggregation: warp per destination node -------------------
__global__ void k_agg128(const float* __restrict__ xw, const float* __restrict__ bias,
                         float* __restrict__ out, int n) {
    int warp = (blockIdx.x * blockDim.x + threadIdx.x) >> 5;
    int lane = threadIdx.x & 31;
    if (warp >= n) return;
    int node = warp;
    int s = g_off[node], e = g_off[node + 1];
    float di = g_dis[node];
    const float4* xw4 = (const float4*)xw;

    float4 acc = xw4[node * 32 + lane];
    int p = s;
    for (; p + 3 < e; p += 4) {
        int s0 = g_srcs[p], s1 = g_srcs[p + 1], s2 = g_srcs[p + 2], s3 = g_srcs[p + 3];
        float4 v0 = xw4[s0 * 32 + lane];
        float4 v1 = xw4[s1 * 32 + lane];
        float4 v2 = xw4[s2 * 32 + lane];
        float4 v3 = xw4[s3 * 32 + lane];
        acc.x += v0.x + v1.x + v2.x + v3.x;
        acc.y += v0.y + v1.y + v2.y + v3.y;
        acc.z += v0.z + v1.z + v2.z + v3.z;
        acc.w += v0.w + v1.w + v2.w + v3.w;
    }
    for (; p < e; p++) {
        int s0 = g_srcs[p];
        float4 v0 = xw4[s0 * 32 + lane];
        acc.x += v0.x; acc.y += v0.y; acc.z += v0.z; acc.w += v0.w;
    }
    float4 bb = ((const float4*)bias)[lane];
    acc.x = fmaxf(di * acc.x + bb.x, 0.f);
    acc.y = fmaxf(di * acc.y + bb.y, 0.f);
    acc.z = fmaxf(di * acc.z + bb.z, 0.f);
    acc.w = fmaxf(di * acc.w + bb.w, 0.f);
    ((float4*)out)[node * 32 + lane] = acc;
}

__global__ void k_agg64(const float* __restrict__ hw, const float* __restrict__ bias,
                        float* __restrict__ out, int n) {
    int warp = (blockIdx.x * blockDim.x + threadIdx.x) >> 5;
    int lane = threadIdx.x & 31;
    if (warp >= n) return;
    int node = warp;
    int s = g_off[node], e = g_off[node + 1];
    float di = g_dis[node];
    const float2* hw2 = (const float2*)hw;

    float2 acc = hw2[node * 32 + lane];
    int p = s;
    for (; p + 3 < e; p += 4) {
        int s0 = g_srcs[p], s1 = g_srcs[p + 1], s2 = g_srcs[p + 2], s3 = g_srcs[p + 3];
        float2 v0 = hw2[s0 * 32 + lane];
        float2 v1 = hw2[s1 * 32 + lane];
        float2 v2 = hw2[s2 * 32 + lane];
        float2 v3 = hw2[s3 * 32 + lane];
        acc.x += v0.x + v1.x + v2.x + v3.x;
        acc.y += v0.y + v1.y + v2.y + v3.y;
    }
    for (; p < e; p++) {
        int s0 = g_srcs[p];
        float2 v0 = hw2[s0 * 32 + lane];
        acc.x += v0.x; acc.y += v0.y;
    }
    float2 bb = ((const float2*)bias)[lane];
    acc.x = di * acc.x + bb.x;
    acc.y = di * acc.y + bb.y;
    ((float2*)out)[node * 32 + lane] = acc;
}

// ---------------- launch ----------------------------------------------------
extern "C" void kernel_launch(void* const* d_in, const int* in_sizes, int n_in,
                              void* d_out, int out_size) {
    const float* x  = (const float*)d_in[0];
    const void*  ei = d_in[1];
    const float* W1 = (const float*)d_in[2];
    const float* b1 = (const float*)d_in[3];
    const float* W2 = (const float*)d_in[4];
    const float* b2 = (const float*)d_in[5];
    float* out = (float*)d_out;

    int n = in_sizes[0] / FIN;
    int E = in_sizes[1] / 2;
    if (n > MAXN) n = MAXN;
    if (E > MAXE) E = MAXE;
    int ntiles = (n + SCAN_TILE - 1) / SCAN_TILE;
    int nbn = (n + 255) / 256;

    float *p_xw, *p_h, *p_hw, *p_dis;
    uint2 *p_wp1, *p_wp2;
    cudaGetSymbolAddress((void**)&p_xw,  g_xw);
    cudaGetSymbolAddress((void**)&p_h,   g_h);
    cudaGetSymbolAddress((void**)&p_hw,  g_hw);
    cudaGetSymbolAddress((void**)&p_dis, g_dis);
    cudaGetSymbolAddress((void**)&p_wp1, g_Wp1);
    cudaGetSymbolAddress((void**)&p_wp2, g_Wp2);

    // dynamic SMEM: A hi/lo only: 2 * 128 rows * 136 bf16 * 2B = 69632
    size_t shg = (size_t)(2 * 128) * 136 * 2;
    cudaFuncSetAttribute(k_gemm_mma<128>, cudaFuncAttributeMaxDynamicSharedMemorySize, (int)shg);
    cudaFuncSetAttribute(k_gemm_mma<64>,  cudaFuncAttributeMaxDynamicSharedMemorySize, (int)shg);

    int gemm_blocks = (n + 127) / 128;

    // preprocessing + layer pipeline (gemm at launch index 3 for ncu)
    k_pre<<<nbn + 96, 256>>>(ei, W1, W2, n, nbn);                          // 0
    k_hist<<<(E + 255) / 256, 256>>>(ei, E);                               // 1
    k_scan1<<<ntiles, 1024>>>(n);                                          // 2
    k_gemm_mma<128><<<gemm_blocks, 256, shg>>>(x, p_wp1, p_dis, p_xw, n);  // 3
    k_scan23<<<(n + 255) / 256, 256>>>(n, ntiles);                         // 4
    k_scatter<<<(E + 255) / 256, 256>>>(ei, E);                            // 5

    k_agg128<<<(n + 7) / 8, 256>>>(p_xw, b1, p_h, n);                      // 6
    k_gemm_mma<64><<<gemm_blocks, 256, shg>>>(p_h, p_wp2, p_dis, p_hw, n); // 7
    k_agg64<<<(n + 7) / 8, 256>>>(p_hw, b2, out, n);                       // 8
}

// round 9
// speedup vs baseline: 1.6933x; 1.1363x over previous
#include <cuda_runtime.h>
#include <cuda_bf16.h>
#include <cstdint>

#define MAXN 50000
#define MAXE 800000
#define FIN  128
#define FHID 128
#define FOUT2 64
#define SCAN_TILE 4096
#define MAXTILES 32

// ---------------- scratch (device globals; no allocation allowed) ----------
__device__ int   g_deg[MAXN];
__device__ int   g_off[MAXN + 1];
__device__ int   g_cur[MAXN];
__device__ float g_dis[MAXN];        // rsqrt(deg+1)
__device__ int   g_srcs[MAXE];
__device__ int   g_is64;
__device__ int   g_tsum[MAXTILES];
__device__ float g_xw[MAXN * FHID];  // dis ⊙ (x @ W1)
__device__ float g_hw[MAXN * FOUT2]; // dis ⊙ (h @ W2)
// h = relu(agg1+b1) stored pre-split as bf16 hi/lo (consumed only by gemm64)
__device__ __nv_bfloat16 g_Hhi[MAXN * FHID];
__device__ __nv_bfloat16 g_Hlo[MAXN * FHID];
// W transposed ([n][k]), bf16 hi/lo packed as uint2 {hi_pair, lo_pair} per k-pair
__device__ uint2 g_Wp1[FHID * FIN / 2];   // 64KB
__device__ uint2 g_Wp2[FOUT2 * FHID / 2]; // 32KB

// ---------------- helpers ----------------------------------------------------
__device__ __forceinline__ int load_idx(const void* ei, long long pos, int is64) {
    if (is64) return (int)((const long long*)ei)[pos];
    return ((const int*)ei)[pos];
}

__device__ __forceinline__ void mma_bf16(float* d, const uint32_t* a,
                                         uint32_t b0, uint32_t b1) {
    asm volatile(
        "mma.sync.aligned.m16n8k16.row.col.f32.bf16.bf16.f32 "
        "{%0,%1,%2,%3}, {%4,%5,%6,%7}, {%8,%9}, {%0,%1,%2,%3};"
        : "+f"(d[0]), "+f"(d[1]), "+f"(d[2]), "+f"(d[3])
        : "r"(a[0]), "r"(a[1]), "r"(a[2]), "r"(a[3]), "r"(b0), "r"(b1));
}

// ---------------- preproc: zero + detect + W -> packed Wt bf16 hi/lo --------
__global__ void k_pre(const void* ei, const float* __restrict__ W1,
                      const float* __restrict__ W2, int n, int nbn) {
    int b = blockIdx.x, tid = threadIdx.x;
    if (b < nbn) {
        int i = b * 256 + tid;
        if (i < n) { g_deg[i] = 0; g_cur[i] = 0; }
        if (b == 0) {
            const long long* p = (const long long*)ei;
            int ok = 1;
            #pragma unroll
            for (int j = 0; j < 8; j++) {
                long long v = p[tid * 8 + j];
                if (v < 0 || v >= (long long)n) ok = 0;
            }
            int all_ok = __syncthreads_and(ok);
            if (tid == 0) g_is64 = all_ok;
        }
    } else if (b < nbn + 64) {            // W1: 16384 elems, [k=128][n=128]
        int e = (b - nbn) * 256 + tid;
        int k = e >> 7, nn = e & 127;
        float w = W1[e];
        __nv_bfloat16 h = __float2bfloat16_rn(w);
        __nv_bfloat16 l = __float2bfloat16_rn(w - __bfloat162float(h));
        unsigned char* base = (unsigned char*)g_Wp1 + (nn * 64 + (k >> 1)) * 8;
        *(__nv_bfloat16*)(base + (k & 1) * 2)     = h;
        *(__nv_bfloat16*)(base + 4 + (k & 1) * 2) = l;
    } else {                               // W2: 8192 elems, [k=128][n=64]
        int e = (b - nbn - 64) * 256 + tid;
        int k = e >> 6, nn = e & 63;
        float w = W2[e];
        __nv_bfloat16 h = __float2bfloat16_rn(w);
        __nv_bfloat16 l = __float2bfloat16_rn(w - __bfloat162float(h));
        unsigned char* base = (unsigned char*)g_Wp2 + (nn * 64 + (k >> 1)) * 8;
        *(__nv_bfloat16*)(base + (k & 1) * 2)     = h;
        *(__nv_bfloat16*)(base + 4 + (k & 1) * 2) = l;
    }
}

__global__ void k_hist(const void* ei, int E) {
    int e = blockIdx.x * blockDim.x + threadIdx.x;
    if (e >= E) return;
    int is64 = g_is64;
    int col = load_idx(ei, (long long)E + e, is64);
    atomicAdd(&g_deg[col], 1);
}

// ---------------- scan phase 1 ----------------------------------------------
__global__ void k_scan1(int n) {
    __shared__ int wsum[32];
    int tid  = threadIdx.x;
    int lane = tid & 31, wid = tid >> 5;
    int base = blockIdx.x * SCAN_TILE + tid * 4;

    int v[4];
    #pragma unroll
    for (int j = 0; j < 4; j++) {
        int i = base + j;
        if (i < n) {
            int d = g_deg[i];
            v[j] = d;
            g_dis[i] = rsqrtf((float)(d + 1));
        } else v[j] = 0;
    }
    int s = v[0] + v[1] + v[2] + v[3];

    int inc = s;
    #pragma unroll
    for (int d = 1; d < 32; d <<= 1) {
        int t = __shfl_up_sync(0xffffffffu, inc, d);
        if (lane >= d) inc += t;
    }
    if (lane == 31) wsum[wid] = inc;
    __syncthreads();
    if (wid == 0) {
        int w = wsum[lane];
        #pragma unroll
        for (int d = 1; d < 32; d <<= 1) {
            int t = __shfl_up_sync(0xffffffffu, w, d);
            if (lane >= d) w += t;
        }
        wsum[lane] = w;
    }
    __syncthreads();
    int excl = inc - s + (wid > 0 ? wsum[wid - 1] : 0);
    int run = excl;
    #pragma unroll
    for (int j = 0; j < 4; j++) {
        int i = base + j;
        if (i < n) g_off[i] = run;
        run += v[j];
    }
    if (tid == 0) g_tsum[blockIdx.x] = wsum[31];
}

// ---------------- scan phases 2+3 merged ------------------------------------
__global__ void k_scan23(int n, int ntiles) {
    __shared__ int sh_toff[32];
    int tid = threadIdx.x;
    if (tid < 32) {
        int t = (tid < ntiles) ? g_tsum[tid] : 0;
        int inc = t;
        #pragma unroll
        for (int d = 1; d < 32; d <<= 1) {
            int u = __shfl_up_sync(0xffffffffu, inc, d);
            if (tid >= d) inc += u;
        }
        sh_toff[tid] = inc - t;
        if (tid == 31 && blockIdx.x == 0) g_off[n] = inc;
    }
    __syncthreads();
    int i = blockIdx.x * blockDim.x + tid;
    if (i < n) g_off[i] += sh_toff[i >> 12];
}

__global__ void k_scatter(const void* ei, int E) {
    int e = blockIdx.x * blockDim.x + threadIdx.x;
    if (e >= E) return;
    int is64 = g_is64;
    int row = load_idx(ei, e, is64);
    int col = load_idx(ei, (long long)E + e, is64);
    int pos = g_off[col] + atomicAdd(&g_cur[col], 1);
    g_srcs[pos] = row;
}

// ---------------- HMMA GEMM: Y = scale[r] * (X[n,128] @ W[128,FO]) ----------
// 3-term bf16 split; mma.sync m16n8k16. 256 thr / 8 warps; M-tile 64.
// Warp grid 2(row)x4(col): warp = 32 rows x FO/4 cols. B from global (L1-hot).
// SRC=0: A from fp32 X (convert in staging). SRC=1: A from pre-split bf16.
template <int FO, int SRC, int OCC>
__global__ void __launch_bounds__(256, OCC)
k_gemm_mma(const float* __restrict__ X,
           const __nv_bfloat16* __restrict__ Xhi,
           const __nv_bfloat16* __restrict__ Xlo,
           const uint2* __restrict__ Wp,
           const float* __restrict__ scale, float* __restrict__ Y, int n) {
    constexpr int NTW = FO / 32;          // n-tiles per warp (4 or 2)
    constexpr int SAS = 136;              // padded bf16 row stride (17 x 16B)
    extern __shared__ char smem[];
    __nv_bfloat16* sAhi = (__nv_bfloat16*)smem;
    __nv_bfloat16* sAlo = sAhi + 64 * SAS;

    int tid = threadIdx.x;
    int row0 = blockIdx.x * 64;

    if (SRC == 0) {
        const float4* X4 = (const float4*)X;
        for (int i = tid; i < 64 * 32; i += 256) {
            int r = i >> 5, c = i & 31;
            int gr = row0 + r;
            float4 f = (gr < n) ? X4[(size_t)gr * 32 + c]
                                : make_float4(0.f, 0.f, 0.f, 0.f);
            __nv_bfloat16 hx = __float2bfloat16_rn(f.x);
            __nv_bfloat16 hy = __float2bfloat16_rn(f.y);
            __nv_bfloat16 hz = __float2bfloat16_rn(f.z);
            __nv_bfloat16 hw = __float2bfloat16_rn(f.w);
            __nv_bfloat162 h0 = __halves2bfloat162(hx, hy);
            __nv_bfloat162 h1 = __halves2bfloat162(hz, hw);
            __nv_bfloat162 l0 = __floats2bfloat162_rn(f.x - __bfloat162float(hx),
                                                      f.y - __bfloat162float(hy));
            __nv_bfloat162 l1 = __floats2bfloat162_rn(f.z - __bfloat162float(hz),
                                                      f.w - __bfloat162float(hw));
            uint32_t* dh = (uint32_t*)(sAhi + r * SAS + c * 4);
            uint32_t* dl = (uint32_t*)(sAlo + r * SAS + c * 4);
            dh[0] = *(uint32_t*)&h0; dh[1] = *(uint32_t*)&h1;
            dl[0] = *(uint32_t*)&l0; dl[1] = *(uint32_t*)&l1;
        }
    } else {
        const uint4* H4 = (const uint4*)Xhi;
        const uint4* L4 = (const uint4*)Xlo;
        const uint4 z4 = make_uint4(0, 0, 0, 0);
        for (int i = tid; i < 64 * 16; i += 256) {
            int r = i >> 4, c = i & 15;
            int gr = row0 + r;
            uint4 hv = (gr < n) ? H4[(size_t)gr * 16 + c] : z4;
            uint4 lv = (gr < n) ? L4[(size_t)gr * 16 + c] : z4;
            *(uint4*)((char*)sAhi + r * 272 + c * 16) = hv;
            *(uint4*)((char*)sAlo + r * 272 + c * 16) = lv;
        }
    }
    __syncthreads();

    int wid = tid >> 5, lane = tid & 31;
    int wr = wid >> 2, wc = wid & 3;
    int g = lane >> 2, t = lane & 3;

    float acc[2][NTW][4];
    #pragma unroll
    for (int rg = 0; rg < 2; rg++)
        #pragma unroll
        for (int nt = 0; nt < NTW; nt++)
            #pragma unroll
            for (int c = 0; c < 4; c++) acc[rg][nt][c] = 0.f;

    #pragma unroll
    for (int k0 = 0; k0 < 128; k0 += 16) {
        uint32_t ahi[2][4], alo[2][4];
        #pragma unroll
        for (int rg = 0; rg < 2; rg++) {
            const __nv_bfloat16* ph = sAhi + (wr * 32 + rg * 16 + g) * SAS + k0 + 2 * t;
            const __nv_bfloat16* pl = sAlo + (wr * 32 + rg * 16 + g) * SAS + k0 + 2 * t;
            ahi[rg][0] = *(const uint32_t*)ph;
            ahi[rg][1] = *(const uint32_t*)(ph + 8 * SAS);
            ahi[rg][2] = *(const uint32_t*)(ph + 8);
            ahi[rg][3] = *(const uint32_t*)(ph + 8 * SAS + 8);
            alo[rg][0] = *(const uint32_t*)pl;
            alo[rg][1] = *(const uint32_t*)(pl + 8 * SAS);
            alo[rg][2] = *(const uint32_t*)(pl + 8);
            alo[rg][3] = *(const uint32_t*)(pl + 8 * SAS + 8);
        }
        #pragma unroll
        for (int nt = 0; nt < NTW; nt++) {
            int ncol = wc * (NTW * 8) + nt * 8 + g;
            const uint2* bp = Wp + ncol * 64 + (k0 >> 1) + t;
            uint2 b0 = __ldg(bp);       // {hi pair, lo pair} at k0+2t
            uint2 b1 = __ldg(bp + 4);   // {hi pair, lo pair} at k0+2t+8
            #pragma unroll
            for (int rg = 0; rg < 2; rg++) {
                mma_bf16(acc[rg][nt], ahi[rg], b0.x, b1.x);
                mma_bf16(acc[rg][nt], ahi[rg], b0.y, b1.y);
                mma_bf16(acc[rg][nt], alo[rg], b0.x, b1.x);
            }
        }
    }

    // epilogue: d0,d1 -> (row, 2t), d2,d3 -> (row+8, 2t); scale per row
    #pragma unroll
    for (int rg = 0; rg < 2; rg++) {
        int r_lo = row0 + wr * 32 + rg * 16 + g;
        int r_hi = r_lo + 8;
        float s0 = (r_lo < n) ? scale[r_lo] : 0.f;
        float s1 = (r_hi < n) ? scale[r_hi] : 0.f;
        #pragma unroll
        for (int nt = 0; nt < NTW; nt++) {
            int col = wc * (NTW * 8) + nt * 8 + 2 * t;
            if (r_lo < n) {
                float2 o = make_float2(acc[rg][nt][0] * s0, acc[rg][nt][1] * s0);
                *(float2*)(Y + (size_t)r_lo * FO + col) = o;
            }
            if (r_hi < n) {
                float2 o = make_float2(acc[rg][nt][2] * s1, acc[rg][nt][3] * s1);
                *(float2*)(Y + (size_t)r_hi * FO + col) = o;
            }
        }
    }
}

// ---------------- aggregation: warp per destination node -------------------
// in pre-scaled by dis: h = relu(di*(sum in[j] + in[i]) + b), stored bf16 hi/lo
__global__ void k_agg128(const float* __restrict__ xw, const float* __restrict__ bias,
                         __nv_bfloat16* __restrict__ Hhi,
                         __nv_bfloat16* __restrict__ Hlo, int n) {
    int warp = (blockIdx.x * blockDim.x + threadIdx.x) >> 5;
    int lane = threadIdx.x & 31;
    if (warp >= n) return;
    int node = warp;
    int s = g_off[node], e = g_off[node + 1];
    float di = g_dis[node];
    const float4* xw4 = (const float4*)xw;

    float4 acc = xw4[node * 32 + lane];
    int p = s;
    for (; p + 3 < e; p += 4) {
        int s0 = g_srcs[p], s1 = g_srcs[p + 1], s2 = g_srcs[p + 2], s3 = g_srcs[p + 3];
        float4 v0 = xw4[s0 * 32 + lane];
        float4 v1 = xw4[s1 * 32 + lane];
        float4 v2 = xw4[s2 * 32 + lane];
        float4 v3 = xw4[s3 * 32 + lane];
        acc.x += v0.x + v1.x + v2.x + v3.x;
        acc.y += v0.y + v1.y + v2.y + v3.y;
        acc.z += v0.z + v1.z + v2.z + v3.z;
        acc.w += v0.w + v1.w + v2.w + v3.w;
    }
    for (; p < e; p++) {
        int s0 = g_srcs[p];
        float4 v0 = xw4[s0 * 32 + lane];
        acc.x += v0.x; acc.y += v0.y; acc.z += v0.z; acc.w += v0.w;
    }
    float4 bb = ((const float4*)bias)[lane];
    acc.x = fmaxf(di * acc.x + bb.x, 0.f);
    acc.y = fmaxf(di * acc.y + bb.y, 0.f);
    acc.z = fmaxf(di * acc.z + bb.z, 0.f);
    acc.w = fmaxf(di * acc.w + bb.w, 0.f);

    __nv_bfloat16 hx = __float2bfloat16_rn(acc.x);
    __nv_bfloat16 hy = __float2bfloat16_rn(acc.y);
    __nv_bfloat16 hz = __float2bfloat16_rn(acc.z);
    __nv_bfloat16 hw = __float2bfloat16_rn(acc.w);
    __nv_bfloat162 h0 = __halves2bfloat162(hx, hy);
    __nv_bfloat162 h1 = __halves2bfloat162(hz, hw);
    __nv_bfloat162 l0 = __floats2bfloat162_rn(acc.x - __bfloat162float(hx),
                                              acc.y - __bfloat162float(hy));
    __nv_bfloat162 l1 = __floats2bfloat162_rn(acc.z - __bfloat162float(hz),
                                              acc.w - __bfloat162float(hw));
    uint2 ho = make_uint2(*(uint32_t*)&h0, *(uint32_t*)&h1);
    uint2 lo = make_uint2(*(uint32_t*)&l0, *(uint32_t*)&l1);
    ((uint2*)Hhi)[node * 32 + lane] = ho;
    ((uint2*)Hlo)[node * 32 + lane] = lo;
}

__global__ void k_agg64(const float* __restrict__ hw, const float* __restrict__ bias,
                        float* __restrict__ out, int n) {
    int warp = (blockIdx.x * blockDim.x + threadIdx.x) >> 5;
    int lane = threadIdx.x & 31;
    if (warp >= n) return;
    int node = warp;
    int s = g_off[node], e = g_off[node + 1];
    float di = g_dis[node];
    const float2* hw2 = (const float2*)hw;

    float2 acc = hw2[node * 32 + lane];
    int p = s;
    for (; p + 3 < e; p += 4) {
        int s0 = g_srcs[p], s1 = g_srcs[p + 1], s2 = g_srcs[p + 2], s3 = g_srcs[p + 3];
        float2 v0 = hw2[s0 * 32 + lane];
        float2 v1 = hw2[s1 * 32 + lane];
        float2 v2 = hw2[s2 * 32 + lane];
        float2 v3 = hw2[s3 * 32 + lane];
        acc.x += v0.x + v1.x + v2.x + v3.x;
        acc.y += v0.y + v1.y + v2.y + v3.y;
    }
    for (; p < e; p++) {
        int s0 = g_srcs[p];
        float2 v0 = hw2[s0 * 32 + lane];
        acc.x += v0.x; acc.y += v0.y;
    }
    float2 bb = ((const float2*)bias)[lane];
    acc.x = di * acc.x + bb.x;
    acc.y = di * acc.y + bb.y;
    ((float2*)out)[node * 32 + lane] = acc;
}

// ---------------- launch ----------------------------------------------------
extern "C" void kernel_launch(void* const* d_in, const int* in_sizes, int n_in,
                              void* d_out, int out_size) {
    const float* x  = (const float*)d_in[0];
    const void*  ei = d_in[1];
    const float* W1 = (const float*)d_in[2];
    const float* b1 = (const float*)d_in[3];
    const float* W2 = (const float*)d_in[4];
    const float* b2 = (const float*)d_in[5];
    float* out = (float*)d_out;

    int n = in_sizes[0] / FIN;
    int E = in_sizes[1] / 2;
    if (n > MAXN) n = MAXN;
    if (E > MAXE) E = MAXE;
    int ntiles = (n + SCAN_TILE - 1) / SCAN_TILE;
    int nbn = (n + 255) / 256;

    float *p_xw, *p_hw, *p_dis;
    __nv_bfloat16 *p_hhi, *p_hlo;
    uint2 *p_wp1, *p_wp2;
    cudaGetSymbolAddress((void**)&p_xw,  g_xw);
    cudaGetSymbolAddress((void**)&p_hw,  g_hw);
    cudaGetSymbolAddress((void**)&p_dis, g_dis);
    cudaGetSymbolAddress((void**)&p_hhi, g_Hhi);
    cudaGetSymbolAddress((void**)&p_hlo, g_Hlo);
    cudaGetSymbolAddress((void**)&p_wp1, g_Wp1);
    cudaGetSymbolAddress((void**)&p_wp2, g_Wp2);

    // dynamic SMEM: A hi/lo: 2 * 64 rows * 136 bf16 * 2B = 34816
    size_t shg = (size_t)(2 * 64) * 136 * 2;
    cudaFuncSetAttribute((const void*)k_gemm_mma<128, 0, 3>,
                         cudaFuncAttributeMaxDynamicSharedMemorySize, (int)shg);
    cudaFuncSetAttribute((const void*)k_gemm_mma<64, 1, 4>,
                         cudaFuncAttributeMaxDynamicSharedMemorySize, (int)shg);

    int gemm_blocks = (n + 63) / 64;

    // preprocessing + layer pipeline (gemm at launch index 3 for ncu)
    k_pre<<<nbn + 96, 256>>>(ei, W1, W2, n, nbn);                          // 0
    k_hist<<<(E + 255) / 256, 256>>>(ei, E);                               // 1
    k_scan1<<<ntiles, 1024>>>(n);                                          // 2
    k_gemm_mma<128, 0, 3><<<gemm_blocks, 256, shg>>>(                      // 3
        x, nullptr, nullptr, p_wp1, p_dis, p_xw, n);
    k_scan23<<<(n + 255) / 256, 256>>>(n, ntiles);                         // 4
    k_scatter<<<(E + 255) / 256, 256>>>(ei, E);                            // 5

    k_agg128<<<(n + 7) / 8, 256>>>(p_xw, b1, p_hhi, p_hlo, n);             // 6
    k_gemm_mma<64, 1, 4><<<gemm_blocks, 256, shg>>>(                       // 7
        nullptr, p_hhi, p_hlo, p_wp2, p_dis, p_hw, n);
    k_agg64<<<(n + 7) / 8, 256>>>(p_hw, b2, out, n);                       // 8
}